// round 2
// baseline (speedup 1.0000x reference)
#include <cuda_runtime.h>
#include <cstdint>

#define TT   64     // t-tile rows per block
#define TM   4      // rows per thread
#define TN   8      // cols per thread
#define NTH  256    // threads per block
#define KDIM 128    // IN
#define ODIM 128    // OUT
#define HS   68     // hsT smem stride (floats), keeps 16B alignment, breaks bank repeat
#define WS   132    // ws  smem stride (floats), 16B aligned

// Load h tile [TT x 128] from feat[node, t0.., :] into smem TRANSPOSED: hsT[k][t]
__device__ __forceinline__ void load_h(const float* __restrict__ feat, int node,
                                       int t0, int T, float* hsT, int tid) {
    const int rowp = tid >> 5;   // 0..7
    const int f4   = tid & 31;   // 0..31 (float4 index along k)
    const float* base = feat + ((size_t)node * T + t0) * KDIM;
#pragma unroll
    for (int p = 0; p < TT / 8; ++p) {
        int row = p * 8 + rowp;
        float4 v = *(const float4*)(base + (size_t)row * KDIM + f4 * 4);
        hsT[(f4 * 4 + 0) * HS + row] = v.x;
        hsT[(f4 * 4 + 1) * HS + row] = v.y;
        hsT[(f4 * 4 + 2) * HS + row] = v.z;
        hsT[(f4 * 4 + 3) * HS + row] = v.w;
    }
}

// Load W [128 x 128] (row-major [k][o]) into smem ws[k][o]
__device__ __forceinline__ void load_w(const float* __restrict__ w, float* ws, int tid) {
    const int rowp = tid >> 5;
    const int f4   = tid & 31;
#pragma unroll
    for (int p = 0; p < KDIM / 8; ++p) {
        int k = p * 8 + rowp;
        float4 v = *(const float4*)(w + (size_t)k * ODIM + f4 * 4);
        *(float4*)(ws + k * WS + f4 * 4) = v;
    }
}

// P = h_tile @ W : each thread computes TM x TN outputs
__device__ __forceinline__ void compute_p(const float* hsT, const float* ws,
                                          int ty, int tx, float p[TM][TN]) {
#pragma unroll
    for (int i = 0; i < TM; i++)
#pragma unroll
        for (int j = 0; j < TN; j++) p[i][j] = 0.f;

#pragma unroll 4
    for (int k = 0; k < KDIM; k++) {
        float4 a  = *(const float4*)(hsT + k * HS + ty * TM);
        float4 b0 = *(const float4*)(ws + k * WS + tx * TN);
        float4 b1 = *(const float4*)(ws + k * WS + tx * TN + 4);
        float av[TM] = {a.x, a.y, a.z, a.w};
        float bv[TN] = {b0.x, b0.y, b0.z, b0.w, b1.x, b1.y, b1.z, b1.w};
#pragma unroll
        for (int i = 0; i < TM; i++)
#pragma unroll
            for (int j = 0; j < TN; j++)
                p[i][j] = fmaf(av[i], bv[j], p[i][j]);
    }
}

__global__ __launch_bounds__(NTH, 2)
void rgcn_kernel(const float* __restrict__ feat,
                 const float* __restrict__ truth,
                 const float* __restrict__ weight,
                 const float* __restrict__ loop_w,
                 const float* __restrict__ bias,
                 const int* __restrict__ src_idx,
                 const int* __restrict__ dst_idx,
                 const int* __restrict__ etypes,
                 float* __restrict__ out,
                 int N, int T, int E) {
    extern __shared__ float smem[];
    float* hsT = smem;                    // KDIM * HS
    float* ws  = hsT + KDIM * HS;         // KDIM * WS
    float* tvs = ws + KDIM * WS;          // TT * 3
    int*   e_src = (int*)(tvs + TT * 3);  // E
    int*   e_dst = e_src + E;             // E
    int*   e_typ = e_dst + E;             // E

    const int n   = blockIdx.x;
    const int t0  = blockIdx.y * TT;
    const int tid = threadIdx.x;
    const int ty  = tid >> 4;   // 0..15 -> rows ty*4..ty*4+3
    const int tx  = tid & 15;   // 0..15 -> cols tx*8..tx*8+7

    // Stage edge index arrays in smem (read uniformly in the edge loop)
    for (int i = tid; i < E; i += NTH) {
        e_src[i] = src_idx[i];
        e_dst[i] = dst_idx[i];
        e_typ[i] = etypes[i];
    }

    float acc[TM][TN];
#pragma unroll
    for (int i = 0; i < TM; i++)
#pragma unroll
        for (int j = 0; j < TN; j++) acc[i][j] = 0.f;

    // ---- Self loop: acc += feat[n] @ loop_weight ----
    load_h(feat, n, t0, T, hsT, tid);
    load_w(loop_w, ws, tid);
    __syncthreads();   // also covers e_src/e_dst/e_typ staging
    {
        float p[TM][TN];
        compute_p(hsT, ws, ty, tx, p);
#pragma unroll
        for (int i = 0; i < TM; i++)
#pragma unroll
            for (int j = 0; j < TN; j++) acc[i][j] += p[i][j];
    }

    // ---- Incoming edges ----
    for (int e = 0; e < E; e++) {
        if (e_dst[e] != n) continue;     // uniform across the block
        const int s  = e_src[e];
        const int et = e_typ[e];

        __syncthreads();                 // previous compute done reading hsT
        load_h(feat, s, t0, T, hsT, tid);
        for (int i = tid; i < TT * 3; i += NTH)
            tvs[i] = truth[((size_t)e * T + t0) * 3 + i];

#pragma unroll 1
        for (int r = 0; r < 3; r++) {
            if (r) __syncthreads();      // previous rule done reading ws
            load_w(weight + (((size_t)et * 3 + r) * KDIM) * ODIM, ws, tid);
            __syncthreads();             // h, tv, W all visible
            float p[TM][TN];
            compute_p(hsT, ws, ty, tx, p);
            float sc[TM];
#pragma unroll
            for (int i = 0; i < TM; i++) sc[i] = tvs[(ty * TM + i) * 3 + r];
#pragma unroll
            for (int i = 0; i < TM; i++)
#pragma unroll
                for (int j = 0; j < TN; j++)
                    acc[i][j] = fmaf(sc[i], p[i][j], acc[i][j]);
        }
    }

    // ---- Epilogue: + bias, single write of the output tile ----
    float bv[TN];
#pragma unroll
    for (int j = 0; j < TN; j++) bv[j] = bias[tx * TN + j];
#pragma unroll
    for (int i = 0; i < TM; i++) {
        int t = t0 + ty * TM + i;
        float* op = out + ((size_t)n * T + t) * ODIM + tx * TN;
        float4 o0 = {acc[i][0] + bv[0], acc[i][1] + bv[1],
                     acc[i][2] + bv[2], acc[i][3] + bv[3]};
        float4 o1 = {acc[i][4] + bv[4], acc[i][5] + bv[5],
                     acc[i][6] + bv[6], acc[i][7] + bv[7]};
        *(float4*)op       = o0;
        *(float4*)(op + 4) = o1;
    }
}

extern "C" void kernel_launch(void* const* d_in, const int* in_sizes, int n_in,
                              void* d_out, int out_size) {
    const float* feat   = (const float*)d_in[0];
    const float* truth  = (const float*)d_in[1];
    const float* weight = (const float*)d_in[2];
    const float* loop_w = (const float*)d_in[3];
    const float* bias   = (const float*)d_in[4];
    const int*   src    = (const int*)d_in[5];
    const int*   dst    = (const int*)d_in[6];
    const int*   etyp   = (const int*)d_in[7];
    float*       out    = (float*)d_out;

    const int E = in_sizes[5];                      // 72
    const int T = in_sizes[1] / (E * 3);            // 4096
    const int N = in_sizes[0] / (T * KDIM);         // 128

    size_t smem_bytes = (size_t)(KDIM * HS + KDIM * WS + TT * 3) * sizeof(float)
                        + (size_t)3 * E * sizeof(int);

    cudaFuncSetAttribute(rgcn_kernel,
                         cudaFuncAttributeMaxDynamicSharedMemorySize,
                         (int)smem_bytes);

    dim3 grid(N, T / TT);
    rgcn_kernel<<<grid, NTH, smem_bytes>>>(feat, truth, weight, loop_w, bias,
                                           src, dst, etyp, out, N, T, E);
}

// round 4
// speedup vs baseline: 3.5757x; 3.5757x over previous
#include <cuda_runtime.h>
#include <cstdint>

#define NTH    256
#define KDIM   128
#define TTILE  128
#define CK_MAX 880
#define GL_MAX 80

// Fragment-packed tf32 weights: [slot(25)][kblk(16)][nblk(16)][lane(32)][reg(2)]
// slot = etype*3 + rule (0..23), slot 24 = loop weight.
__device__ float g_wb[25 * 128 * 128];

__device__ __forceinline__ uint32_t cvt_tf32(float f) {
    uint32_t u;
    asm("cvt.rna.tf32.f32 %0, %1;" : "=r"(u) : "f"(f));
    return u;
}
__device__ __forceinline__ uint32_t smem_u32(const void* p) {
    uint32_t a;
    asm("{ .reg .u64 t; cvta.to.shared.u64 t, %1; cvt.u32.u64 %0, t; }" : "=r"(a) : "l"(p));
    return a;
}

// ---- prep: transpose-free fragment packing + tf32 rounding of all weights ----
__global__ void prep_w(const float* __restrict__ w, const float* __restrict__ lw) {
    int idx = blockIdx.x * blockDim.x + threadIdx.x;
    if (idx >= 25 * 16384) return;
    int s = idx >> 14, rem = idx & 16383;
    int i = rem >> 7, o = rem & 127;           // B[k=i][n=o]
    float v = (s < 24) ? w[(size_t)(s * 128 + i) * 128 + o] : lw[i * 128 + o];
    int lane = (o & 7) * 4 + (i & 3);          // m16n8k8 .col B-fragment mapping
    int reg  = (i >> 2) & 1;
    int flat = (((s * 16 + (i >> 3)) * 16 + (o >> 3)) * 32 + lane) * 2 + reg;
    g_wb[flat] = __uint_as_float(cvt_tf32(v));
}

// ---- main kernel ----
__global__ __launch_bounds__(NTH, 2)
void rgcn_mma(const float* __restrict__ feat, const float* __restrict__ truth,
              const float* __restrict__ bias,
              const int* __restrict__ src_idx, const int* __restrict__ dst_idx,
              const int* __restrict__ etypes, float* __restrict__ out,
              int N, int T, int E) {
    extern __shared__ char smraw[];
    float* As = (float*)smraw;      // 2 x 4096 floats (double-buffered A chunk)
    float* Bs = As + 8192;          // 2 x 4096 floats (double-buffered B chunk)
    int*   ck = (int*)(Bs + 8192);  // chunk descriptors
    int*   gl = ck + CK_MAX;        // per-CTA incident-edge list
    int*   cnt = gl + GL_MAX;

    const int n    = blockIdx.x;
    const int t0   = blockIdx.y * TTILE;
    const int tid  = threadIdx.x;
    const int lane = tid & 31;
    const int warp = tid >> 5;
    const int wm   = warp & 3;      // M quarter (32 rows)
    const int wn   = warp >> 2;     // N half (64 cols)

    if (tid == 0) cnt[0] = 0;
    __syncthreads();
    if (tid < E && dst_idx[tid] == n) {
        int p = atomicAdd(cnt, 1);
        gl[p] = src_idx[tid] | (etypes[tid] << 8) | (tid << 16);
    }
    __syncthreads();
    const int ne = cnt[0];
    const int nc = ne * 12 + 4;     // 12 chunks per edge (3 rules x 4 k-chunks), 4 for self

    // Build flat chunk list: bits [0:8)=src [8:13)=bslot [13:15)=kc [15:22)=edge [22:24)=rule
    for (int i = tid; i < nc; i += NTH) {
        int g = i / 12, v;
        if (g < ne) {
            int rem = i - g * 12;
            int kc = rem / 3, r = rem - kc * 3;   // kc outer, r inner (feat L1 reuse)
            int e = gl[g];
            v = (e & 0xFF) | ((((e >> 8) & 0xFF) * 3 + r) << 8) | (kc << 13)
              | ((e >> 16) << 15) | (r << 22);
        } else {
            int kc = i - ne * 12;
            v = n | (24 << 8) | (kc << 13);
        }
        ck[i] = v;
    }
    __syncthreads();

    float acc[2][8][4];
#pragma unroll
    for (int mi = 0; mi < 2; mi++)
#pragma unroll
        for (int ni = 0; ni < 8; ni++)
#pragma unroll
            for (int q = 0; q < 4; q++) acc[mi][ni][q] = 0.f;

    const uint32_t Bs_a = smem_u32(Bs);

    // ---------------- fill one chunk (A: scaled+tf32 STS, B: cp.async) -------
    auto fill = [&](int c, int buf) {
        int info  = ck[c];
        int src   = info & 0xFF;
        int bslot = (info >> 8) & 0x1F;
        int kc    = (info >> 13) & 3;
        int eid   = (info >> 15) & 0x7F;
        int r     = (info >> 22) & 3;

        // B: 16KB contiguous copy from fragment-packed global
        const char* gsrc = (const char*)(g_wb + (size_t)(bslot * 16 + kc * 4) * 1024) + tid * 16;
        uint32_t bdst = Bs_a + buf * 16384 + tid * 16;
#pragma unroll
        for (int u = 0; u < 4; u++)
            asm volatile("cp.async.cg.shared.global [%0], [%1], 16;"
                         :: "r"(bdst + u * 4096), "l"(gsrc + u * 4096));

        // A: thread covers t = tid/2, i = (tid&1)*16 .. +15 of this 32-k chunk
        int t = tid >> 1, i0 = (tid & 1) * 16;
        float sc = 1.0f;
        if (bslot != 24) sc = __ldg(&truth[((size_t)eid * T + t0 + t) * 3 + r]);
        const float4* fp = (const float4*)(feat + ((size_t)src * T + t0 + t) * KDIM + kc * 32 + i0);
        int mblk = t >> 4, r4 = t & 15;
        float* ab = As + buf * 4096;
#pragma unroll
        for (int u = 0; u < 4; u++) {
            float4 vv = fp[u];
            int i    = i0 + u * 4;
            int reg  = (r4 >> 3) + ((i >> 1) & 2);
            int base = ((i >> 3) * 8 + mblk) * 128 + (r4 & 7) * 4 + reg;
            ab[base +  0] = __uint_as_float(cvt_tf32(vv.x * sc));
            ab[base + 32] = __uint_as_float(cvt_tf32(vv.y * sc));
            ab[base + 64] = __uint_as_float(cvt_tf32(vv.z * sc));
            ab[base + 96] = __uint_as_float(cvt_tf32(vv.w * sc));
        }
    };

    // ---------------- compute one chunk (4 x k8 steps) -----------------------
    auto comp = [&](int buf) {
        const float* ab = As + buf * 4096;
        const float* bb = Bs + buf * 4096;
        const int perm = ((lane & 3) << 3) | (lane >> 2);
#pragma unroll
        for (int kb = 0; kb < 4; kb++) {
            uint4 a[2];
#pragma unroll
            for (int mi = 0; mi < 2; mi++)
                a[mi] = *(const uint4*)(ab + ((kb * 8 + wm * 2 + mi) * 32 + perm) * 4);
            uint2 b[8];
#pragma unroll
            for (int ni = 0; ni < 8; ni++)
                b[ni] = *(const uint2*)(bb + ((kb * 16 + wn * 8 + ni) * 32 + lane) * 2);
#pragma unroll
            for (int mi = 0; mi < 2; mi++)
#pragma unroll
                for (int ni = 0; ni < 8; ni++)
                    asm volatile(
                        "mma.sync.aligned.m16n8k8.row.col.f32.tf32.tf32.f32 "
                        "{%0,%1,%2,%3}, {%4,%5,%6,%7}, {%8,%9}, {%0,%1,%2,%3};"
                        : "+f"(acc[mi][ni][0]), "+f"(acc[mi][ni][1]),
                          "+f"(acc[mi][ni][2]), "+f"(acc[mi][ni][3])
                        : "r"(a[mi].x), "r"(a[mi].y), "r"(a[mi].z), "r"(a[mi].w),
                          "r"(b[ni].x), "r"(b[ni].y));
        }
    };

    // ---------------- software pipeline over the whole chunk stream ----------
    fill(0, 0);
    asm volatile("cp.async.commit_group;" ::: "memory");
    asm volatile("cp.async.wait_group 0;" ::: "memory");
    __syncthreads();
    for (int c = 0; c < nc; c++) {
        int buf = c & 1;
        if (c + 1 < nc) fill(c + 1, buf ^ 1);
        asm volatile("cp.async.commit_group;" ::: "memory");
        comp(buf);
        asm volatile("cp.async.wait_group 0;" ::: "memory");
        __syncthreads();
    }

    // ---------------- epilogue: + bias, single write --------------------------
    const int row_base = wm * 32 + (lane >> 2);
    const int col_base = wn * 64 + (lane & 3) * 2;
#pragma unroll
    for (int mi = 0; mi < 2; mi++) {
        float* o0 = out + ((size_t)n * T + t0 + row_base + mi * 16) * KDIM;
#pragma unroll
        for (int ni = 0; ni < 8; ni++) {
            int col = col_base + ni * 8;
            float2 bv = *(const float2*)(bias + col);
            float2 v0 = {acc[mi][ni][0] + bv.x, acc[mi][ni][1] + bv.y};
            float2 v1 = {acc[mi][ni][2] + bv.x, acc[mi][ni][3] + bv.y};
            *(float2*)(o0 + col)             = v0;
            *(float2*)(o0 + 8 * KDIM + col)  = v1;
        }
    }
}

// ---------------- launch ----------------
extern "C" void kernel_launch(void* const* d_in, const int* in_sizes, int n_in,
                              void* d_out, int out_size) {
    const float* feat   = (const float*)d_in[0];
    const float* truth  = (const float*)d_in[1];
    const float* weight = (const float*)d_in[2];
    const float* loop_w = (const float*)d_in[3];
    const float* bias   = (const float*)d_in[4];
    const int*   src    = (const int*)d_in[5];
    const int*   dst    = (const int*)d_in[6];
    const int*   etyp   = (const int*)d_in[7];
    float*       out    = (float*)d_out;

    const int E = in_sizes[5];
    const int T = in_sizes[1] / (E * 3);
    const int N = in_sizes[0] / (T * KDIM);

    prep_w<<<(25 * 16384 + 255) / 256, 256>>>(weight, loop_w);

    size_t smem = (size_t)(8192 + 8192) * 4 + (size_t)(CK_MAX + GL_MAX + 8) * 4;
    cudaFuncSetAttribute(rgcn_mma, cudaFuncAttributeMaxDynamicSharedMemorySize, (int)smem);
    dim3 grid(N, T / TTILE);
    rgcn_mma<<<grid, NTH, smem>>>(feat, truth, bias, src, dst, etyp, out, N, T, E);
}

// round 5
// speedup vs baseline: 6.7196x; 1.8792x over previous
#include <cuda_runtime.h>
#include <cuda_fp16.h>
#include <cstdint>

#define NTH    256
#define KDIM   128
#define TTILE  128
#define CK_MAX 880
#define GL_MAX 80

// fp16 fragment-packed weights:
// [slot(25)][kc(4)][kb(2)][wn(2)][q(4)][lane(32)][pos(4)][half(2)]
// slot = etype*3 + rule, slot 24 = loop weight.
__device__ __half g_wb[25 * 16384];

__device__ __forceinline__ uint32_t smem_u32(const void* p) {
    uint32_t a;
    asm("{ .reg .u64 t; cvta.to.shared.u64 t, %1; cvt.u32.u64 %0, t; }" : "=r"(a) : "l"(p));
    return a;
}
__device__ __forceinline__ uint32_t pk2(float a, float b) {
    __half2 h = __floats2half2_rn(a, b);
    return *reinterpret_cast<uint32_t*>(&h);
}

// ---- prep: fragment packing + fp16 rounding of all weights ----
__global__ void prep_w(const float* __restrict__ w, const float* __restrict__ lw) {
    int idx = blockIdx.x * blockDim.x + threadIdx.x;
    if (idx >= 25 * 16384) return;
    int s = idx >> 14, rem = idx & 16383;
    int i = rem >> 7, o = rem & 127;              // B[k=i][n=o]
    float v = (s < 24) ? w[(size_t)s * 16384 + i * 128 + o] : lw[i * 128 + o];
    // m16n8k16 .col B-fragment mapping
    int kc = i >> 5, kw = i & 31, kb = kw >> 4, k16 = kw & 15;
    int reg = k16 >> 3, kr = k16 & 7;
    int lane = (o & 7) * 4 + (kr >> 1), hi = kr & 1;
    int wn = o >> 6, ni = (o >> 3) & 7, q = ni >> 1, pos = (ni & 1) * 2 + reg;
    int flat = ((((((s * 4 + kc) * 2 + kb) * 2 + wn) * 4 + q) * 32 + lane) * 4 + pos) * 2 + hi;
    g_wb[flat] = __float2half_rn(v);
}

// ---- main kernel ----
__global__ __launch_bounds__(NTH, 2)
void rgcn_mma(const float* __restrict__ feat, const float* __restrict__ truth,
              const float* __restrict__ bias,
              const int* __restrict__ src_idx, const int* __restrict__ dst_idx,
              const int* __restrict__ etypes, float* __restrict__ out,
              int N, int T, int E) {
    extern __shared__ char smraw[];
    char* As = smraw;               // 2 x 8192 B (fp16 A chunk, [t][32k], SW64)
    char* Bs = smraw + 16384;       // 2 x 8192 B (fp16 B chunk, fragment-packed)
    int*  ck = (int*)(smraw + 32768);
    int*  gl = ck + CK_MAX;
    int*  cnt = gl + GL_MAX;

    const int n    = blockIdx.x;
    const int t0   = blockIdx.y * TTILE;
    const int tid  = threadIdx.x;
    const int lane = tid & 31;
    const int warp = tid >> 5;
    const int wm   = warp & 3;      // 32-row M quarter
    const int wn   = warp >> 2;     // 64-col N half

    if (tid == 0) cnt[0] = 0;
    __syncthreads();
    if (tid < E && dst_idx[tid] == n) {
        int p = atomicAdd(cnt, 1);
        gl[p] = src_idx[tid] | (etypes[tid] << 8) | (tid << 16);
    }
    __syncthreads();
    const int ne = cnt[0];
    const int nc = ne * 12 + 4;

    // chunk descriptors: [0:8)=src [8:13)=bslot [13:15)=kc [15:22)=edge [22:24)=rule
    for (int i = tid; i < nc; i += NTH) {
        int g = i / 12, v;
        if (g < ne) {
            int rem = i - g * 12;
            int kc = rem / 3, r = rem - kc * 3;
            int e = gl[g];
            v = (e & 0xFF) | ((((e >> 8) & 0xFF) * 3 + r) << 8) | (kc << 13)
              | ((e >> 16) << 15) | (r << 22);
        } else {
            int kc = i - ne * 12;
            v = n | (24 << 8) | (kc << 13);
        }
        ck[i] = v;
    }
    __syncthreads();

    float acc[2][8][4];
#pragma unroll
    for (int mi = 0; mi < 2; mi++)
#pragma unroll
        for (int ni = 0; ni < 8; ni++)
#pragma unroll
            for (int q = 0; q < 4; q++) acc[mi][ni][q] = 0.f;

    const uint32_t As_u = smem_u32(As);
    const uint32_t Bs_u = smem_u32(Bs);

    float  sc;
    float4 fr[4];

    // issue A global loads + tv for chunk (held in regs across comp)
    auto a_load = [&](int info) {
        int src = info & 0xFF, bslot = (info >> 8) & 0x1F, kc = (info >> 13) & 3;
        int eid = (info >> 15) & 0x7F, r = (info >> 22) & 3;
        int t = tid >> 1;
        sc = 1.0f;
        if (bslot != 24) sc = __ldg(&truth[((size_t)eid * T + t0 + t) * 3 + r]);
        const float4* fp = (const float4*)(feat + ((size_t)src * T + t0 + t) * KDIM
                                           + kc * 32 + (tid & 1) * 16);
        fr[0] = fp[0]; fr[1] = fp[1]; fr[2] = fp[2]; fr[3] = fp[3];
    };
    // B: 8KB contiguous cp.async from fragment-packed global
    auto b_fill = [&](int info, int buf) {
        int bslot = (info >> 8) & 0x1F, kc = (info >> 13) & 3;
        const char* gs = (const char*)g_wb + ((size_t)(bslot * 4 + kc)) * 8192 + tid * 16;
        uint32_t bd = Bs_u + buf * 8192 + tid * 16;
        asm volatile("cp.async.cg.shared.global [%0], [%1], 16;" :: "r"(bd), "l"(gs));
        asm volatile("cp.async.cg.shared.global [%0], [%1], 16;" :: "r"(bd + 4096), "l"(gs + 4096));
    };
    // scale + cvt + store A (SW64 swizzled rows)
    auto a_store = [&](int buf) {
        uint4 p0, p1;
        p0.x = pk2(fr[0].x * sc, fr[0].y * sc); p0.y = pk2(fr[0].z * sc, fr[0].w * sc);
        p0.z = pk2(fr[1].x * sc, fr[1].y * sc); p0.w = pk2(fr[1].z * sc, fr[1].w * sc);
        p1.x = pk2(fr[2].x * sc, fr[2].y * sc); p1.y = pk2(fr[2].z * sc, fr[2].w * sc);
        p1.z = pk2(fr[3].x * sc, fr[3].y * sc); p1.w = pk2(fr[3].z * sc, fr[3].w * sc);
        uint32_t off0 = (tid >> 1) * 64 + (tid & 1) * 32;
        uint32_t off1 = off0 + 16;
        *(uint4*)(As + buf * 8192 + (off0 ^ ((off0 >> 3) & 0x30))) = p0;
        *(uint4*)(As + buf * 8192 + (off1 ^ ((off1 >> 3) & 0x30))) = p1;
    };

    auto comp = [&](int buf) {
        const uint32_t ab_u = As_u + buf * 8192;
        const uint4* bb = (const uint4*)(Bs + buf * 8192);
#pragma unroll
        for (int kb = 0; kb < 2; kb++) {
            uint32_t a[2][4];
#pragma unroll
            for (int mi = 0; mi < 2; mi++) {
                int tl = wm * 32 + mi * 16 + ((lane >> 3) & 1) * 8 + (lane & 7);
                int ka = kb * 2 + (lane >> 4);
                uint32_t off = (uint32_t)(tl * 64 + ka * 16);
                off ^= (off >> 3) & 0x30;
                asm volatile("ldmatrix.sync.aligned.m8n8.x4.shared.b16 {%0,%1,%2,%3}, [%4];"
                    : "=r"(a[mi][0]), "=r"(a[mi][1]), "=r"(a[mi][2]), "=r"(a[mi][3])
                    : "r"(ab_u + off));
            }
            const uint4* bp = bb + ((kb * 2 + wn) * 4) * 32 + lane;
            uint4 bq0 = bp[0], bq1 = bp[32], bq2 = bp[64], bq3 = bp[96];
            const uint4 bq[4] = {bq0, bq1, bq2, bq3};
#pragma unroll
            for (int mi = 0; mi < 2; mi++)
#pragma unroll
                for (int ni = 0; ni < 8; ni++) {
                    uint32_t b0 = (ni & 1) ? bq[ni >> 1].z : bq[ni >> 1].x;
                    uint32_t b1 = (ni & 1) ? bq[ni >> 1].w : bq[ni >> 1].y;
                    asm volatile(
                        "mma.sync.aligned.m16n8k16.row.col.f32.f16.f16.f32 "
                        "{%0,%1,%2,%3},{%4,%5,%6,%7},{%8,%9},{%0,%1,%2,%3};"
                        : "+f"(acc[mi][ni][0]), "+f"(acc[mi][ni][1]),
                          "+f"(acc[mi][ni][2]), "+f"(acc[mi][ni][3])
                        : "r"(a[mi][0]), "r"(a[mi][1]), "r"(a[mi][2]), "r"(a[mi][3]),
                          "r"(b0), "r"(b1));
                }
        }
    };

    // ---------------- pipeline ----------------
    int info = ck[0];
    b_fill(info, 0);
    a_load(info);
    a_store(0);
    asm volatile("cp.async.commit_group;" ::: "memory");
    asm volatile("cp.async.wait_group 0;" ::: "memory");
    __syncthreads();

    for (int c = 0; c < nc; c++) {
        int buf = c & 1;
        bool pre = (c + 1 < nc);
        if (pre) {
            info = ck[c + 1];
            b_fill(info, buf ^ 1);   // async B
            a_load(info);            // LDGs in flight during comp
        }
        comp(buf);
        if (pre) a_store(buf ^ 1);   // cvt+STS after latency hidden
        asm volatile("cp.async.commit_group;" ::: "memory");
        asm volatile("cp.async.wait_group 0;" ::: "memory");
        __syncthreads();
    }

    // ---------------- epilogue: + bias, single write ----------------
    const int row_base = wm * 32 + (lane >> 2);
    const int col_base = wn * 64 + (lane & 3) * 2;
#pragma unroll
    for (int mi = 0; mi < 2; mi++) {
        float* o0 = out + ((size_t)n * T + t0 + row_base + mi * 16) * KDIM;
#pragma unroll
        for (int ni = 0; ni < 8; ni++) {
            int col = col_base + ni * 8;
            float2 bv = *(const float2*)(bias + col);
            float2 v0 = {acc[mi][ni][0] + bv.x, acc[mi][ni][1] + bv.y};
            float2 v1 = {acc[mi][ni][2] + bv.x, acc[mi][ni][3] + bv.y};
            *(float2*)(o0 + col)            = v0;
            *(float2*)(o0 + 8 * KDIM + col) = v1;
        }
    }
}

// ---------------- launch ----------------
extern "C" void kernel_launch(void* const* d_in, const int* in_sizes, int n_in,
                              void* d_out, int out_size) {
    const float* feat   = (const float*)d_in[0];
    const float* truth  = (const float*)d_in[1];
    const float* weight = (const float*)d_in[2];
    const float* loop_w = (const float*)d_in[3];
    const float* bias   = (const float*)d_in[4];
    const int*   src    = (const int*)d_in[5];
    const int*   dst    = (const int*)d_in[6];
    const int*   etyp   = (const int*)d_in[7];
    float*       out    = (float*)d_out;

    const int E = in_sizes[5];
    const int T = in_sizes[1] / (E * 3);
    const int N = in_sizes[0] / (T * KDIM);

    prep_w<<<(25 * 16384 + 255) / 256, 256>>>(weight, loop_w);

    size_t smem = 32768 + (size_t)(CK_MAX + GL_MAX + 8) * 4;
    cudaFuncSetAttribute(rgcn_mma, cudaFuncAttributeMaxDynamicSharedMemorySize, (int)smem);
    dim3 grid(N, T / TTILE);
    rgcn_mma<<<grid, NTH, smem>>>(feat, truth, bias, src, dst, etyp, out, N, T, E);
}